// round 1
// baseline (speedup 1.0000x reference)
#include <cuda_runtime.h>
#include <math.h>

#define TRAJ_NUM 8
#define EVAL     30
#define PTS      (TRAJ_NUM*EVAL)   // 240 points per group
#define SGM_T    2.0f
#define D0c      0.5f
#define Rc       0.3f
#define VOX      0.2f

#define MAXG 512
#define MAXB (MAXG*TRAJ_NUM)

// scratch (no allocations allowed)
__device__ float g_pos[MAXB*EVAL*3];
__device__ int   g_mn0[MAXG*3];
__device__ int   g_mx0[MAXG*3];
__device__ int   g_mn [MAXG*3];
__device__ int   g_ls [MAXG*3];

// ---------------------------------------------------------------------------
// Kernel A: positions + per-group min/max box (trunc'd to voxel ints)
// one block per group, 256 threads (240 active)
// ---------------------------------------------------------------------------
__global__ void __launch_bounds__(256)
kernA(const float* __restrict__ Df, const float* __restrict__ Dp,
      const float* __restrict__ L,  const float* __restrict__ min_bounds,
      const int* __restrict__ map_id)
{
    int g = blockIdx.x;
    int t = threadIdx.x;

    __shared__ float Ls[36];
    __shared__ float red[256];
    if (t < 36) Ls[t] = L[t];
    __syncthreads();

    float p[3] = {0.f, 0.f, 0.f};
    bool act = (t < PTS);
    if (act) {
        int traj = t / EVAL;
        int n    = t % EVAL;
        int b    = g * TRAJ_NUM + traj;

        // t_n like jnp.linspace(dt, T, EVAL)
        float start = SGM_T / (float)EVAL;
        float step  = (SGM_T - start) / (float)(EVAL - 1);
        float tn    = start + (float)n * step;

        float tp[6];
        tp[0] = 1.f;
        #pragma unroll
        for (int k = 1; k < 6; k++) tp[k] = tp[k-1] * tn;

        #pragma unroll
        for (int i = 0; i < 3; i++) {
            float d[6];
            d[0] = Df[b*9 + i*3 + 0];
            d[1] = Df[b*9 + i*3 + 1];
            d[2] = Df[b*9 + i*3 + 2];
            d[3] = Dp[b*9 + i*3 + 0];
            d[4] = Dp[b*9 + i*3 + 1];
            d[5] = Dp[b*9 + i*3 + 2];
            float s = 0.f;
            #pragma unroll
            for (int j = 0; j < 6; j++) {
                float c = 0.f;
                #pragma unroll
                for (int k = 0; k < 6; k++) c += Ls[j*6 + k] * d[k];
                s += tp[j] * c;
            }
            p[i] = s;
        }
        int idx = (b*EVAL + n) * 3;
        g_pos[idx+0] = p[0];
        g_pos[idx+1] = p[1];
        g_pos[idx+2] = p[2];
    }

    int mid = map_id[g];
    #pragma unroll
    for (int i = 0; i < 3; i++) {
        float mb = min_bounds[mid*3 + i];
        // min
        red[t] = act ? p[i] : 3.4e38f;
        __syncthreads();
        for (int s = 128; s > 0; s >>= 1) {
            if (t < s) red[t] = fminf(red[t], red[t+s]);
            __syncthreads();
        }
        if (t == 0) g_mn0[g*3 + i] = (int)truncf((red[0] - mb) / VOX);
        __syncthreads();
        // max
        red[t] = act ? p[i] : -3.4e38f;
        __syncthreads();
        for (int s = 128; s > 0; s >>= 1) {
            if (t < s) red[t] = fmaxf(red[t], red[t+s]);
            __syncthreads();
        }
        if (t == 0) g_mx0[g*3 + i] = (int)truncf((red[0] - mb) / VOX);
        __syncthreads();
    }
}

// ---------------------------------------------------------------------------
// Kernel B: cross-group box logic (max_spans reduce -> clamp -> shift reduce)
// single block, one thread per group (blockDim = pow2 >= G)
// ---------------------------------------------------------------------------
__global__ void kernB(const float* __restrict__ sdf_shapes,
                      const int* __restrict__ map_id, int G)
{
    int g = threadIdx.x;
    bool act = (g < G);
    __shared__ int red[1024];

    int mid = act ? map_id[g] : 0;
    int mn0[3], mx0[3], shp[3];
    #pragma unroll
    for (int i = 0; i < 3; i++) {
        mn0[i] = act ? g_mn0[g*3 + i] : 0;
        mx0[i] = act ? g_mx0[g*3 + i] : 0;
        shp[i] = (int)sdf_shapes[mid*3 + i];
    }

    // max_spans = (mx - mn).max over groups
    int ms[3];
    #pragma unroll
    for (int i = 0; i < 3; i++) {
        red[threadIdx.x] = act ? (mx0[i] - mn0[i]) : 0;
        __syncthreads();
        for (int s = blockDim.x >> 1; s > 0; s >>= 1) {
            if (threadIdx.x < s) red[threadIdx.x] = max(red[threadIdx.x], red[threadIdx.x + s]);
            __syncthreads();
        }
        ms[i] = red[0];
        __syncthreads();
    }

    int mn[3], mx[3];
    #pragma unroll
    for (int i = 0; i < 3; i++) {
        int c = (mn0[i] + mx0[i]) >> 1;         // floor div (matches jnp //)
        mn[i] = c - (ms[i] >> 1) - 5;
        mx[i] = c + (ms[i] >> 1) + 5;
        int nmn = max(mn[i], 0);
        mx[i] += nmn - mn[i]; mn[i] = nmn;
        int nmx = min(mx[i], shp[i]);
        mn[i] -= mx[i] - nmx; mx[i] = nmx;
    }

    // shift = max over groups of max(-min(mn,0), 0)
    int shift[3];
    #pragma unroll
    for (int i = 0; i < 3; i++) {
        red[threadIdx.x] = act ? max(-min(mn[i], 0), 0) : 0;
        __syncthreads();
        for (int s = blockDim.x >> 1; s > 0; s >>= 1) {
            if (threadIdx.x < s) red[threadIdx.x] = max(red[threadIdx.x], red[threadIdx.x + s]);
            __syncthreads();
        }
        shift[i] = red[0];
        __syncthreads();
    }

    if (act) {
        #pragma unroll
        for (int i = 0; i < 3; i++) {
            int m = mn[i] + shift[i];
            g_mn[g*3 + i] = m;
            g_ls[g*3 + i] = mx[i] - m;
        }
    }
}

// ---------------------------------------------------------------------------
// Kernel D: trilinear SDF sampling + exp cost + per-trajectory sum
// one block per group, 240 threads (one per point)
// ---------------------------------------------------------------------------
__global__ void __launch_bounds__(PTS)
kernD(const float* __restrict__ sdf, const float* __restrict__ min_bounds,
      const float* __restrict__ sdf_shapes, const int* __restrict__ map_id,
      float* __restrict__ out)
{
    int g = blockIdx.x;
    int t = threadIdx.x;

    __shared__ float cs[PTS];

    int mid = map_id[g];
    int mn0 = g_mn[g*3+0], mn1 = g_mn[g*3+1], mn2 = g_mn[g*3+2];
    int ls0 = g_ls[g*3+0], ls1 = g_ls[g*3+1], ls2 = g_ls[g*3+2];
    float mb0 = min_bounds[mid*3+0];
    float mb1 = min_bounds[mid*3+1];
    float mb2 = min_bounds[mid*3+2];
    int Wm = (int)sdf_shapes[0];
    int Hm = (int)sdf_shapes[1];
    int Dm = (int)sdf_shapes[2];
    long base = (long)mid * Dm * Hm * Wm;

    int traj = t / EVAL;
    int n    = t % EVAL;
    int b    = g * TRAJ_NUM + traj;
    int pidx = (b*EVAL + n) * 3;

    float ox = (float)mn0 * VOX + mb0;
    float oy = (float)mn1 * VOX + mb1;
    float oz = (float)mn2 * VOX + mb2;

    float gx = (g_pos[pidx+0] - ox) / VOX;
    float gy = (g_pos[pidx+1] - oy) / VOX;
    float gz = (g_pos[pidx+2] - oz) / VOX;

    float gpx = 2.f * gx / (float)(ls0 - 1) - 1.f;
    float gpy = 2.f * gy / (float)(ls1 - 1) - 1.f;
    float gpz = 2.f * gz / (float)(ls2 - 1) - 1.f;
    bool valid = (gpx <  0.99f) && (gpx > -0.99f) &&
                 (gpy <  0.99f) && (gpy > -0.99f) &&
                 (gpz <  0.99f) && (gpz > -0.99f);

    float fx0 = floorf(gx), fy0 = floorf(gy), fz0 = floorf(gz);
    int l0x = (int)fx0, l0y = (int)fy0, l0z = (int)fz0;
    float f0 = gx - fx0, f1 = gy - fy0, f2 = gz - fz0;

    float wx[2] = {1.f - f0, f0};
    float wy[2] = {1.f - f1, f1};
    float wz[2] = {1.f - f2, f2};

    float acc = 0.f;
    #pragma unroll
    for (int dx = 0; dx < 2; dx++)
    #pragma unroll
    for (int dy = 0; dy < 2; dy++)
    #pragma unroll
    for (int dz = 0; dz < 2; dz++) {
        int ilx = l0x + dx, ily = l0y + dy, ilz = l0z + dz;
        bool inb = (ilx >= 0) && (ilx < ls0) &&
                   (ily >= 0) && (ily < ls1) &&
                   (ilz >= 0) && (ilz < ls2);
        int igx = min(max(ilx + mn0, 0), Wm - 1);
        int igy = min(max(ily + mn1, 0), Hm - 1);
        int igz = min(max(ilz + mn2, 0), Dm - 1);
        float val = __ldg(&sdf[base + ((long)igz * Hm + igy) * Wm + igx]);
        float w = wx[dx] * wy[dy] * wz[dz];
        acc += inb ? w * val : 0.f;
    }

    float cost = valid ? expf(-(acc - D0c) / Rc) : 0.f;
    cs[t] = cost;
    __syncthreads();

    if (t < TRAJ_NUM) {
        float dt = SGM_T / (float)EVAL;
        float s = 0.f;
        #pragma unroll
        for (int k = 0; k < EVAL; k++) s += cs[t*EVAL + k] * dt;
        out[g*TRAJ_NUM + t] = s;
    }
}

// ---------------------------------------------------------------------------
extern "C" void kernel_launch(void* const* d_in, const int* in_sizes, int n_in,
                              void* d_out, int out_size)
{
    const float* Df         = (const float*)d_in[0];
    const float* Dp         = (const float*)d_in[1];
    const float* L          = (const float*)d_in[2];
    const float* sdf_maps   = (const float*)d_in[3];
    const float* min_bounds = (const float*)d_in[4];
    const float* sdf_shapes = (const float*)d_in[5];
    const int*   map_id     = (const int*)d_in[6];

    int G = in_sizes[6];

    kernA<<<G, 256>>>(Df, Dp, L, min_bounds, map_id);

    int nt = 1;
    while (nt < G) nt <<= 1;
    if (nt > 1024) nt = 1024;
    kernB<<<1, nt>>>(sdf_shapes, map_id, G);

    kernD<<<G, PTS>>>(sdf_maps, min_bounds, sdf_shapes, map_id, (float*)d_out);
}

// round 2
// speedup vs baseline: 1.3266x; 1.3266x over previous
#include <cuda_runtime.h>
#include <math.h>

#define TRAJ_NUM 8
#define EVAL     30
#define PTS      (TRAJ_NUM*EVAL)   // 240 points per group
#define SGM_T    2.0f
#define D0c      0.5f
#define Rc       0.3f
#define VOX      0.2f
#define INV_VOX  5.0f

#define MAXG 1024

// scratch (no allocations allowed)
__device__ int g_mn0[MAXG*3];
__device__ int g_mx0[MAXG*3];

// replay-safe grid barrier state: g_count returns to 0 every barrier,
// g_gen grows monotonically (only compared for inequality).
__device__ unsigned int g_count = 0;
__device__ volatile unsigned int g_gen = 0;

__device__ __forceinline__ float warpMinF(float v) {
    #pragma unroll
    for (int o = 16; o > 0; o >>= 1) v = fminf(v, __shfl_xor_sync(0xffffffff, v, o));
    return v;
}
__device__ __forceinline__ float warpMaxF(float v) {
    #pragma unroll
    for (int o = 16; o > 0; o >>= 1) v = fmaxf(v, __shfl_xor_sync(0xffffffff, v, o));
    return v;
}
__device__ __forceinline__ int warpMaxI(int v) {
    #pragma unroll
    for (int o = 16; o > 0; o >>= 1) v = max(v, __shfl_xor_sync(0xffffffff, v, o));
    return v;
}

__global__ void __launch_bounds__(256, 2)
fused_kernel(const float* __restrict__ Df, const float* __restrict__ Dp,
             const float* __restrict__ L,  const float* __restrict__ sdf,
             const float* __restrict__ min_bounds,
             const float* __restrict__ sdf_shapes,
             const int* __restrict__ map_id,
             float* __restrict__ out, int G)
{
    const int g    = blockIdx.x;
    const int t    = threadIdx.x;
    const int wid  = t >> 5;
    const int lane = t & 31;

    __shared__ float Ls[36];
    __shared__ float wmin[8][3], wmax[8][3];
    __shared__ int   wredA[8][3], wredB[8][3];
    __shared__ int   s_maxspan[3], s_shift[3];
    __shared__ float cs[PTS];

    if (t < 36) Ls[t] = L[t];
    __syncthreads();

    // ---------------- Phase 1: position (registers) + group AABB ----------
    const bool act = (t < PTS);
    float p[3] = {0.f, 0.f, 0.f};
    if (act) {
        int traj = t / EVAL;
        int n    = t % EVAL;
        int b    = g * TRAJ_NUM + traj;

        float start = SGM_T / (float)EVAL;
        float step  = (SGM_T - start) / (float)(EVAL - 1);
        float tn    = start + (float)n * step;

        float tp[6];
        tp[0] = 1.f;
        #pragma unroll
        for (int k = 1; k < 6; k++) tp[k] = tp[k-1] * tn;

        #pragma unroll
        for (int i = 0; i < 3; i++) {
            float d[6];
            d[0] = Df[b*9 + i*3 + 0];
            d[1] = Df[b*9 + i*3 + 1];
            d[2] = Df[b*9 + i*3 + 2];
            d[3] = Dp[b*9 + i*3 + 0];
            d[4] = Dp[b*9 + i*3 + 1];
            d[5] = Dp[b*9 + i*3 + 2];
            float s = 0.f;
            #pragma unroll
            for (int j = 0; j < 6; j++) {
                float c = 0.f;
                #pragma unroll
                for (int k = 0; k < 6; k++) c += Ls[j*6 + k] * d[k];
                s += tp[j] * c;
            }
            p[i] = s;
        }
    }

    int mid = map_id[g];
    float mb[3];
    #pragma unroll
    for (int i = 0; i < 3; i++) mb[i] = min_bounds[mid*3 + i];

    // shuffle reduce (sentinels for inactive lanes)
    #pragma unroll
    for (int i = 0; i < 3; i++) {
        float vmin = act ? p[i] :  3.4e38f;
        float vmax = act ? p[i] : -3.4e38f;
        vmin = warpMinF(vmin);
        vmax = warpMaxF(vmax);
        if (lane == 0) { wmin[wid][i] = vmin; wmax[wid][i] = vmax; }
    }
    __syncthreads();
    if (t < 3) {           // thread i reduces dim i over 8 warps
        float vmin =  3.4e38f, vmax = -3.4e38f;
        #pragma unroll
        for (int w = 0; w < 8; w++) {
            vmin = fminf(vmin, wmin[w][t]);
            vmax = fmaxf(vmax, wmax[w][t]);
        }
        g_mn0[g*3 + t] = (int)truncf((vmin - mb[t]) * INV_VOX);
        g_mx0[g*3 + t] = (int)truncf((vmax - mb[t]) * INV_VOX);
    }
    __syncthreads();

    // ---------------- grid barrier (replay-safe) ---------------------------
    if (t == 0) {
        __threadfence();
        unsigned int gen = g_gen;
        if (atomicAdd(&g_count, 1) == gridDim.x - 1) {
            g_count = 0;
            __threadfence();
            g_gen = gen + 1;
        } else {
            while (g_gen == gen) { }
        }
        __threadfence();
    }
    __syncthreads();

    // ---------------- Phase 2: redundant cross-group box logic -------------
    // thread t handles group t (G <= blockDim assumed; G=256 here)
    int span[3] = {0, 0, 0};
    int tm0[3]  = {0, 0, 0}, tx0[3] = {0, 0, 0}, tshp[3] = {1, 1, 1};
    bool gact = (t < G);
    if (gact) {
        int tmid = map_id[t];
        #pragma unroll
        for (int i = 0; i < 3; i++) {
            tm0[i]  = g_mn0[t*3 + i];
            tx0[i]  = g_mx0[t*3 + i];
            tshp[i] = (int)sdf_shapes[tmid*3 + i];
            span[i] = tx0[i] - tm0[i];
        }
    }
    // max over groups of span
    #pragma unroll
    for (int i = 0; i < 3; i++) {
        int v = warpMaxI(span[i]);
        if (lane == 0) wredA[wid][i] = v;
    }
    __syncthreads();
    if (t < 3) {
        int v = -2147483647;
        #pragma unroll
        for (int w = 0; w < 8; w++) v = max(v, wredA[w][t]);
        s_maxspan[t] = v;
    }
    __syncthreads();

    // clamped mn for group t -> shift contribution
    int sc[3] = {0, 0, 0};
    if (gact) {
        #pragma unroll
        for (int i = 0; i < 3; i++) {
            int c  = (tm0[i] + tx0[i]) >> 1;
            int ms = s_maxspan[i];
            int mn = c - (ms >> 1) - 5;
            int mx = c + (ms >> 1) + 5;
            int nmn = max(mn, 0);
            mx += nmn - mn; mn = nmn;
            int nmx = min(mx, tshp[i]);
            mn -= mx - nmx;
            sc[i] = max(-min(mn, 0), 0);
        }
    }
    #pragma unroll
    for (int i = 0; i < 3; i++) {
        int v = warpMaxI(sc[i]);
        if (lane == 0) wredB[wid][i] = v;
    }
    __syncthreads();
    if (t < 3) {
        int v = -2147483647;
        #pragma unroll
        for (int w = 0; w < 8; w++) v = max(v, wredB[w][t]);
        s_shift[t] = v;
    }
    __syncthreads();

    // own group's final box (all threads compute identically)
    int mn[3], ls[3], shp[3];
    #pragma unroll
    for (int i = 0; i < 3; i++) {
        int m0 = g_mn0[g*3 + i];
        int x0 = g_mx0[g*3 + i];
        shp[i] = (int)sdf_shapes[mid*3 + i];
        int c  = (m0 + x0) >> 1;
        int ms = s_maxspan[i];
        int m  = c - (ms >> 1) - 5;
        int x  = c + (ms >> 1) + 5;
        int nm = max(m, 0);
        x += nm - m; m = nm;
        int nx = min(x, shp[i]);
        m -= x - nx; x = nx;
        m += s_shift[i];
        mn[i] = m;
        ls[i] = x - m;
    }

    // ---------------- Phase 3: trilinear SDF sample + cost -----------------
    int Wm = shp[0], Hm = shp[1], Dm = shp[2];
    long base = (long)mid * Dm * Hm * Wm;

    float cost = 0.f;
    if (act) {
        float gx = (p[0] - ((float)mn[0] * VOX + mb[0])) * INV_VOX;
        float gy = (p[1] - ((float)mn[1] * VOX + mb[1])) * INV_VOX;
        float gz = (p[2] - ((float)mn[2] * VOX + mb[2])) * INV_VOX;

        float gpx = 2.f * gx / (float)(ls[0] - 1) - 1.f;
        float gpy = 2.f * gy / (float)(ls[1] - 1) - 1.f;
        float gpz = 2.f * gz / (float)(ls[2] - 1) - 1.f;
        bool valid = (gpx <  0.99f) && (gpx > -0.99f) &&
                     (gpy <  0.99f) && (gpy > -0.99f) &&
                     (gpz <  0.99f) && (gpz > -0.99f);

        float fx0 = floorf(gx), fy0 = floorf(gy), fz0 = floorf(gz);
        int l0x = (int)fx0, l0y = (int)fy0, l0z = (int)fz0;
        float f0 = gx - fx0, f1 = gy - fy0, f2 = gz - fz0;

        float wx[2] = {1.f - f0, f0};
        float wy[2] = {1.f - f1, f1};
        float wz[2] = {1.f - f2, f2};

        float acc = 0.f;
        #pragma unroll
        for (int dx = 0; dx < 2; dx++)
        #pragma unroll
        for (int dy = 0; dy < 2; dy++)
        #pragma unroll
        for (int dz = 0; dz < 2; dz++) {
            int ilx = l0x + dx, ily = l0y + dy, ilz = l0z + dz;
            bool inb = (ilx >= 0) && (ilx < ls[0]) &&
                       (ily >= 0) && (ily < ls[1]) &&
                       (ilz >= 0) && (ilz < ls[2]);
            int igx = min(max(ilx + mn[0], 0), Wm - 1);
            int igy = min(max(ily + mn[1], 0), Hm - 1);
            int igz = min(max(ilz + mn[2], 0), Dm - 1);
            float val = __ldg(&sdf[base + ((long)igz * Hm + igy) * Wm + igx]);
            float w = wx[dx] * wy[dy] * wz[dz];
            acc += inb ? w * val : 0.f;
        }

        cost = valid ? __expf(-(acc - D0c) / Rc) : 0.f;
    }
    if (act) cs[t] = cost;
    __syncthreads();

    if (t < TRAJ_NUM) {
        const float dt = SGM_T / (float)EVAL;
        float s = 0.f;
        #pragma unroll
        for (int k = 0; k < EVAL; k++) s += cs[t*EVAL + k];
        out[g*TRAJ_NUM + t] = s * dt;
    }
}

// ---------------------------------------------------------------------------
extern "C" void kernel_launch(void* const* d_in, const int* in_sizes, int n_in,
                              void* d_out, int out_size)
{
    const float* Df         = (const float*)d_in[0];
    const float* Dp         = (const float*)d_in[1];
    const float* L          = (const float*)d_in[2];
    const float* sdf_maps   = (const float*)d_in[3];
    const float* min_bounds = (const float*)d_in[4];
    const float* sdf_shapes = (const float*)d_in[5];
    const int*   map_id     = (const int*)d_in[6];

    int G = in_sizes[6];

    fused_kernel<<<G, 256>>>(Df, Dp, L, sdf_maps, min_bounds, sdf_shapes,
                             map_id, (float*)d_out, G);
}